// round 8
// baseline (speedup 1.0000x reference)
#include <cuda_runtime.h>
#include <cuda_fp16.h>
#include <cstdint>

#define NN 100000
#define EE 1600000
#define GG 512
#define DD 128
#define CC 10
#define EPS 1e-5f
#define SB 1024
#define NSB ((NN + SB - 1) / SB)

typedef unsigned long long u64;

// ---------------- device scratch ----------------
__device__ float  g_h[NN * DD];
__device__ __half2 g_h16[NN * (DD / 2)];   // h * ns, fp16, for aggregation gathers
__device__ float  g_X[NN * DD];
__device__ float  g_t[NN];                 // sum of ns over in-edges
__device__ float  g_ns[NN];
__device__ float  g_nd[NN];
__device__ int    g_degO[NN];
__device__ int    g_degI[NN];
__device__ int    g_off[NN + 1];
__device__ int    g_cur[NN];
__device__ int    g_esrc[EE];
__device__ int    g_bsum[128];
__device__ int    g_boff[128];
__device__ float  g_sum[DD], g_sq[DD];
__device__ float  g_avec[DD];
__device__ float  g_Wd[DD * 288];          // duplicated W: [k][tx*18 + c], c<16, w[n]=dup pairs
__device__ float  g_cvec[DD], g_bias2[DD];
__device__ float  g_hg[GG * DD], g_hg2[GG * DD];
__device__ float  g_psum[DD], g_psq[DD], g_fsum[DD], g_fsq[DD];

// ---------------- f32x2 helpers ----------------
__device__ __forceinline__ u64 pack2(float lo, float hi) {
    u64 r; asm("mov.b64 %0,{%1,%2};" : "=l"(r) : "f"(lo), "f"(hi)); return r;
}
__device__ __forceinline__ void unpack2(u64 v, float& lo, float& hi) {
    asm("mov.b64 {%0,%1},%2;" : "=f"(lo), "=f"(hi) : "l"(v));
}
__device__ __forceinline__ void fma2(u64& d, u64 a, u64 b) {
    asm("fma.rn.f32x2 %0,%1,%2,%0;" : "+l"(d) : "l"(a), "l"(b));
}

// ---------------- init ----------------
__global__ void init_kernel() {
    int i = blockIdx.x * blockDim.x + threadIdx.x;
    if (i < NN) { g_degO[i] = 0; g_degI[i] = 0; g_t[i] = 0.f; }
    if (i < DD) {
        g_sum[i] = 0.f; g_sq[i] = 0.f;
        g_psum[i] = 0.f; g_psq[i] = 0.f;
        g_fsum[i] = 0.f; g_fsq[i] = 0.f;
    }
}

__global__ void degree_kernel(const int* __restrict__ src, const int* __restrict__ dst) {
    int e = blockIdx.x * blockDim.x + threadIdx.x;
    if (e < EE) {
        atomicAdd(&g_degO[src[e]], 1);
        atomicAdd(&g_degI[dst[e]], 1);
    }
}

// ---------------- 3-pass scan over g_degI ----------------
__global__ void scan1_kernel() {
    __shared__ int wsum[8];
    int b = blockIdx.x, tid = threadIdx.x;
    int base = b * SB + tid * 4;
    int s = 0;
    #pragma unroll
    for (int u = 0; u < 4; u++) { int i = base + u; if (i < NN) s += g_degI[i]; }
    int lane = tid & 31, wid = tid >> 5;
    #pragma unroll
    for (int o = 16; o > 0; o >>= 1) s += __shfl_down_sync(0xffffffffu, s, o);
    if (lane == 0) wsum[wid] = s;
    __syncthreads();
    if (tid == 0) {
        int t = 0;
        #pragma unroll
        for (int w = 0; w < 8; w++) t += wsum[w];
        g_bsum[b] = t;
    }
}

__global__ void scan2_kernel() {
    __shared__ int ws[4];
    int tid = threadIdx.x;
    int lane = tid & 31, wid = tid >> 5;
    int v = (tid < NSB) ? g_bsum[tid] : 0;
    int x = v;
    #pragma unroll
    for (int o = 1; o < 32; o <<= 1) {
        int y = __shfl_up_sync(0xffffffffu, x, o);
        if (lane >= o) x += y;
    }
    if (lane == 31) ws[wid] = x;
    __syncthreads();
    if (tid == 0) {
        int c = 0;
        #pragma unroll
        for (int w = 0; w < 4; w++) { int t = ws[w]; ws[w] = c; c += t; }
    }
    __syncthreads();
    int excl = x - v + ws[wid];
    if (tid < NSB) g_boff[tid] = excl;
    if (tid == 0) g_off[NN] = EE;
}

__global__ void scan3_kernel() {
    __shared__ int wsum[8];
    int b = blockIdx.x, tid = threadIdx.x;
    int base = b * SB + tid * 4;
    int v[4];
    #pragma unroll
    for (int u = 0; u < 4; u++) {
        int i = base + u;
        v[u] = (i < NN) ? g_degI[i] : 0;
    }
    int tot = v[0] + v[1] + v[2] + v[3];
    int lane = tid & 31, wid = tid >> 5;
    int x = tot;
    #pragma unroll
    for (int o = 1; o < 32; o <<= 1) {
        int y = __shfl_up_sync(0xffffffffu, x, o);
        if (lane >= o) x += y;
    }
    if (lane == 31) wsum[wid] = x;
    __syncthreads();
    if (wid == 0 && lane < 8) {
        int w = wsum[lane];
        int xx = w;
        #pragma unroll
        for (int o = 1; o < 8; o <<= 1) {
            int y = __shfl_up_sync(0xffu, xx, o);
            if (lane >= o) xx += y;
        }
        wsum[lane] = xx - w;
    }
    __syncthreads();
    int p = x - tot + wsum[wid] + g_boff[b];
    #pragma unroll
    for (int u = 0; u < 4; u++) {
        int i = base + u;
        if (i < NN) {
            g_off[i] = p; g_cur[i] = p; p += v[u];
            g_nd[i] = rsqrtf((float)max(v[u], 1));
            g_ns[i] = rsqrtf((float)max(g_degO[i], 1));
        }
    }
}

// fill CSR + accumulate sum of ns[src] per dst
__global__ void fill_kernel(const int* __restrict__ src, const int* __restrict__ dst) {
    int e = blockIdx.x * blockDim.x + threadIdx.x;
    if (e < EE) {
        int s = src[e], d = dst[e];
        int p = atomicAdd(&g_cur[d], 1);
        g_esrc[p] = s;
        atomicAdd(&g_t[d], g_ns[s]);
    }
}

// ---------------- BN stats over external input (feat layer only) ----------------
__global__ void stats_in_kernel(const float* __restrict__ x) {
    int c = threadIdx.x;
    float s = 0.f, q = 0.f;
    for (int r = blockIdx.x; r < NN; r += gridDim.x) {
        float v = x[r * DD + c];
        s += v; q += v * v;
    }
    atomicAdd(&g_sum[c], s);
    atomicAdd(&g_sq[c], q);
}

// ---------------- finprep: BN finalize, a -> g_avec, bias/cvec, reset stats ----------------
__global__ void finprep_kernel(const float* __restrict__ g, const float* __restrict__ b,
                               const float* __restrict__ W, const float* __restrict__ addb,
                               int mode) {
    __shared__ float sbv[DD];
    __shared__ float red[8][DD];
    int tid = threadIdx.x;
    if (tid < DD) {
        float m = g_sum[tid] * (1.0f / NN);
        float v = g_sq[tid] * (1.0f / NN) - m * m;
        float a = g[tid] * rsqrtf(v + EPS);
        g_avec[tid] = a;
        sbv[tid] = b[tid] - m * a;
    }
    __syncthreads();
    int n = tid & 127, part = tid >> 7;
    float s = 0.f;
    for (int k = part * 16; k < part * 16 + 16; k++)
        s += sbv[k] * W[k * DD + n];
    red[part][n] = s;
    __syncthreads();
    if (tid < DD) {
        float t = 0.f;
        #pragma unroll
        for (int p = 0; p < 8; p++) t += red[p][n];
        if (mode == 0) g_bias2[n] = addb[n] + t;
        else         { g_cvec[n] = t; g_bias2[n] = addb[n]; }
        g_sum[n] = 0.f; g_sq[n] = 0.f;
    }
}

// ---------------- prep_wd: duplicated, BN-folded W ----------------
// g_Wd[k*288 + tx*18 + c] = a[k] * W[k][tx*8 + c/2]   (c = 0..15)
__global__ void prep_wd_kernel(const float* __restrict__ W) {
    int k = blockIdx.x, t = threadIdx.x;   // 256 threads
    int tx = t >> 4, c = t & 15;
    float a = g_avec[k];
    g_Wd[k * 288 + tx * 18 + c] = a * W[k * DD + tx * 8 + (c >> 1)];
}

// ---------------- edge aggregation (fp16 gathers, pre-scaled by ns) ----------------
__global__ void agg_kernel() {
    int warp = (blockIdx.x * blockDim.x + threadIdx.x) >> 5;
    int lane = threadIdx.x & 31;
    if (warp >= NN) return;
    int beg = g_off[warp], end = g_off[warp + 1];
    float a0 = 0.f, a1 = 0.f, a2 = 0.f, a3 = 0.f;
    const uint2* __restrict__ h2 = (const uint2*)g_h16;
    for (int e = beg; e < end; e++) {
        int s = g_esrc[e];
        uint2 hv = h2[(size_t)s * 32 + lane];
        float2 f0 = __half22float2(*(__half2*)&hv.x);
        float2 f1 = __half22float2(*(__half2*)&hv.y);
        a0 += f0.x; a1 += f0.y; a2 += f1.x; a3 += f1.y;
    }
    float nd = g_nd[warp];
    ((float4*)g_X)[warp * 32 + lane] = make_float4(a0 * nd, a1 * nd, a2 * nd, a3 * nd);
}

// ---------------- main GEMM (f32x2, m-paired acc, duplicated W) ----------------
// smem: Xs[32][132] at 0 (16896B), Ws2[32][288] at 4224 floats (36864B). total 53760B.
#define XS(k, m)  smem[(k) * 132 + (m)]
#define WS2(k, c) smem[4224 + (k) * 288 + (c)]

template <bool RESID, bool HAST, bool XG, bool STATS, bool WH16>
__global__ void __launch_bounds__(256, 2)
gemm_kernel(const float* __restrict__ Xext, int nrows) {
    extern __shared__ float smem[];
    const float* __restrict__ X = XG ? g_X : Xext;
    int tid = threadIdx.x;
    int m0g = blockIdx.x * 128;
    int tx = tid & 15, ty = tid >> 4;
    int mm = ty * 8, nn = tx * 8;
    u64 acc[4][8];   // [m-pair][n]
    #pragma unroll
    for (int i = 0; i < 4; i++)
        #pragma unroll
        for (int j = 0; j < 8; j++) acc[i][j] = 0ull;

    for (int kc = 0; kc < 4; kc++) {
        int k0 = kc * 32;
        // X tile: transpose with rotation (2-way max conflict)
        #pragma unroll
        for (int it = 0; it < 4; it++) {
            int idx = tid + it * 256;
            int row = idx >> 3, kq = idx & 7;
            int gr = m0g + row;
            float4 v = make_float4(0.f, 0.f, 0.f, 0.f);
            if (gr < nrows) v = *(const float4*)(X + gr * DD + k0 + kq * 4);
            float vv[4] = {v.x, v.y, v.z, v.w};
            #pragma unroll
            for (int c = 0; c < 4; c++) {
                int cc = (c + kq) & 3;
                XS(kq * 4 + cc, row) = vv[cc];
            }
        }
        // W tile: 32 rows x 288 floats = 2304 float4
        for (int i = tid; i < 2304; i += 256) {
            int row = i / 72, col = i - row * 72;
            *(float4*)&WS2(row, col * 4) = ((const float4*)(g_Wd + (k0 + row) * 288))[col];
        }
        __syncthreads();
        #pragma unroll 8
        for (int k = 0; k < 32; k++) {
            ulonglong2 xa = *(const ulonglong2*)&XS(k, mm);
            ulonglong2 xb = *(const ulonglong2*)&XS(k, mm + 4);
            u64 xp[4] = {xa.x, xa.y, xb.x, xb.y};
            u64 w[8];
            #pragma unroll
            for (int j = 0; j < 8; j++)
                w[j] = *(const u64*)&WS2(k, tx * 18 + 2 * j);
            #pragma unroll
            for (int i = 0; i < 4; i++)
                #pragma unroll
                for (int j = 0; j < 8; j++)
                    fma2(acc[i][j], xp[i], w[j]);
        }
        __syncthreads();
    }

    // epilogue: per m-pair, unpack two rows; n = nn..nn+7 consecutive
    float colsum[8], colsq[8];
    #pragma unroll
    for (int j = 0; j < 8; j++) { colsum[j] = 0.f; colsq[j] = 0.f; }

    float bias[8], cv[8];
    #pragma unroll
    for (int j = 0; j < 8; j++) {
        bias[j] = g_bias2[nn + j];
        cv[j] = HAST ? g_cvec[nn + j] : 0.f;
    }

    #pragma unroll
    for (int i = 0; i < 4; i++) {
        float vr[2][8];
        #pragma unroll
        for (int j = 0; j < 8; j++) unpack2(acc[i][j], vr[0][j], vr[1][j]);
        #pragma unroll
        for (int half = 0; half < 2; half++) {
            int row = m0g + mm + 2 * i + half;
            if (row >= nrows) continue;
            float tval = HAST ? g_t[row] * g_nd[row] : 0.f;
            float nsv = WH16 ? g_ns[row] : 0.f;
            float o[8];
            #pragma unroll
            for (int j = 0; j < 8; j++) {
                float v = vr[half][j] + bias[j];
                if (HAST) v += tval * cv[j];
                o[j] = fmaxf(v, 0.f);
            }
            float4* hp = (float4*)(g_h + row * DD + nn);
            if (RESID) {
                float4 o0 = hp[0], o1 = hp[1];
                o[0] += o0.x; o[1] += o0.y; o[2] += o0.z; o[3] += o0.w;
                o[4] += o1.x; o[5] += o1.y; o[6] += o1.z; o[7] += o1.w;
            }
            hp[0] = make_float4(o[0], o[1], o[2], o[3]);
            hp[1] = make_float4(o[4], o[5], o[6], o[7]);
            if (WH16) {
                __half2 hh[4];
                #pragma unroll
                for (int j = 0; j < 4; j++)
                    hh[j] = __floats2half2_rn(o[2 * j] * nsv, o[2 * j + 1] * nsv);
                *(uint4*)(g_h16 + row * 64 + tx * 4) = *(uint4*)hh;
            }
            if (STATS) {
                #pragma unroll
                for (int j = 0; j < 8; j++) {
                    colsum[j] += o[j]; colsq[j] += o[j] * o[j];
                }
            }
        }
    }

    if (STATS) {
        float* sred = smem;          // 2048 floats
        float* sqd  = smem + 4224;   // 2048 floats (Ws2 area)
        __syncthreads();
        #pragma unroll
        for (int j = 0; j < 8; j++) {
            sred[ty * 128 + nn + j] = colsum[j];
            sqd[ty * 128 + nn + j]  = colsq[j];
        }
        __syncthreads();
        if (tid < 128) {
            float s = 0.f, q = 0.f;
            #pragma unroll
            for (int t2 = 0; t2 < 16; t2++) {
                s += sred[t2 * 128 + tid];
                q += sqd[t2 * 128 + tid];
            }
            atomicAdd(&g_sum[tid], s);
            atomicAdd(&g_sq[tid], q);
        }
    }
}

// ---------------- pooling + head ----------------
__global__ void pool_kernel(const int* __restrict__ gid) {
    int g = blockIdx.x, c = threadIdx.x;
    int lo = 0, hi = NN;
    while (lo < hi) { int mid = (lo + hi) >> 1; if (gid[mid] < g) lo = mid + 1; else hi = mid; }
    int s0 = lo;
    lo = s0; hi = NN;
    while (lo < hi) { int mid = (lo + hi) >> 1; if (gid[mid] < g + 1) lo = mid + 1; else hi = mid; }
    int s1 = lo;
    float s = 0.f;
    for (int r = s0; r < s1; r++) s += g_h[r * DD + c];
    g_hg[g * DD + c] = s;
    atomicAdd(&g_psum[c], s);
    atomicAdd(&g_psq[c], s * s);
}

__global__ void fc_kernel(const float* __restrict__ W, const float* __restrict__ bias,
                          const float* __restrict__ gma, const float* __restrict__ bta) {
    __shared__ float x[DD];
    int r = blockIdx.x, c = threadIdx.x;
    float m = g_psum[c] * (1.0f / GG);
    float v = g_psq[c] * (1.0f / GG) - m * m;
    float a = gma[c] * rsqrtf(v + EPS);
    float bv = bta[c] - m * a;
    x[c] = g_hg[r * DD + c] * a + bv;
    __syncthreads();
    float s = bias[c];
    #pragma unroll 8
    for (int k = 0; k < DD; k++) s += x[k] * W[k * DD + c];
    float o = fmaxf(s, 0.f);
    g_hg2[r * DD + c] = o;
    atomicAdd(&g_fsum[c], o);
    atomicAdd(&g_fsq[c], o * o);
}

__global__ void cls_kernel(const float* __restrict__ W, const float* __restrict__ bias,
                           const float* __restrict__ gma, const float* __restrict__ bta,
                           float* __restrict__ out) {
    __shared__ float x[DD];
    int r = blockIdx.x, c = threadIdx.x;
    float m = g_fsum[c] * (1.0f / GG);
    float v = g_fsq[c] * (1.0f / GG) - m * m;
    float a = gma[c] * rsqrtf(v + EPS);
    float bv = bta[c] - m * a;
    x[c] = g_hg2[r * DD + c] * a + bv;
    __syncthreads();
    if (c < CC) {
        float s = bias[c];
        for (int k = 0; k < DD; k++) s += x[k] * W[k * CC + c];
        out[r * CC + c] = s;
    }
}

// ---------------- launch ----------------
#define GEMM_SMEM 53760

extern "C" void kernel_launch(void* const* d_in, const int* in_sizes, int n_in,
                              void* d_out, int out_size) {
    const float* h_in      = (const float*)d_in[0];
    const float* bn_feat_g = (const float*)d_in[1];
    const float* bn_feat_b = (const float*)d_in[2];
    const float* feat_W    = (const float*)d_in[3];
    const float* feat_b    = (const float*)d_in[4];
    const float* conv_bn_g = (const float*)d_in[5];
    const float* conv_bn_b = (const float*)d_in[6];
    const float* conv_W    = (const float*)d_in[7];
    const float* conv_b    = (const float*)d_in[8];
    const float* fc_bn_g   = (const float*)d_in[9];
    const float* fc_bn_b   = (const float*)d_in[10];
    const float* fc_W      = (const float*)d_in[11];
    const float* fc_b      = (const float*)d_in[12];
    const float* bn_hid_g  = (const float*)d_in[13];
    const float* bn_hid_b  = (const float*)d_in[14];
    const float* cls_W     = (const float*)d_in[15];
    const float* cls_b     = (const float*)d_in[16];
    const int*   src       = (const int*)d_in[17];
    const int*   dst       = (const int*)d_in[18];
    const int*   gid       = (const int*)d_in[19];
    float* out = (float*)d_out;

    const int nblkN = (NN + 255) / 256;
    const int nblkE = (EE + 255) / 256;
    const int gemmBlks = (NN + 127) / 128;

    static int attr_done = 0;
    if (!attr_done) {
        cudaFuncSetAttribute(gemm_kernel<false, false, false, true, true>,
                             cudaFuncAttributeMaxDynamicSharedMemorySize, GEMM_SMEM);
        cudaFuncSetAttribute(gemm_kernel<true, true, true, true, true>,
                             cudaFuncAttributeMaxDynamicSharedMemorySize, GEMM_SMEM);
        cudaFuncSetAttribute(gemm_kernel<true, true, true, false, false>,
                             cudaFuncAttributeMaxDynamicSharedMemorySize, GEMM_SMEM);
        attr_done = 1;
    }

    // graph structure
    init_kernel<<<nblkN, 256>>>();
    degree_kernel<<<nblkE, 256>>>(src, dst);
    scan1_kernel<<<NSB, 256>>>();
    scan2_kernel<<<1, 128>>>();
    scan3_kernel<<<NSB, 256>>>();
    fill_kernel<<<nblkE, 256>>>(src, dst);

    // feat layer
    stats_in_kernel<<<512, DD>>>(h_in);
    finprep_kernel<<<1, 1024>>>(bn_feat_g, bn_feat_b, feat_W, feat_b, 0);
    prep_wd_kernel<<<DD, 256>>>(feat_W);
    gemm_kernel<false, false, false, true, true><<<gemmBlks, 256, GEMM_SMEM>>>(h_in, NN);

    // conv layers
    finprep_kernel<<<1, 1024>>>(conv_bn_g + 0 * DD, conv_bn_b + 0 * DD, conv_W + 0 * DD * DD, conv_b + 0 * DD, 1);
    prep_wd_kernel<<<DD, 256>>>(conv_W + 0 * DD * DD);
    agg_kernel<<<(NN * 32 + 255) / 256, 256>>>();
    gemm_kernel<true, true, true, true, true><<<gemmBlks, 256, GEMM_SMEM>>>(nullptr, NN);

    finprep_kernel<<<1, 1024>>>(conv_bn_g + 1 * DD, conv_bn_b + 1 * DD, conv_W + 1 * DD * DD, conv_b + 1 * DD, 1);
    prep_wd_kernel<<<DD, 256>>>(conv_W + 1 * DD * DD);
    agg_kernel<<<(NN * 32 + 255) / 256, 256>>>();
    gemm_kernel<true, true, true, true, true><<<gemmBlks, 256, GEMM_SMEM>>>(nullptr, NN);

    finprep_kernel<<<1, 1024>>>(conv_bn_g + 2 * DD, conv_bn_b + 2 * DD, conv_W + 2 * DD * DD, conv_b + 2 * DD, 1);
    prep_wd_kernel<<<DD, 256>>>(conv_W + 2 * DD * DD);
    agg_kernel<<<(NN * 32 + 255) / 256, 256>>>();
    gemm_kernel<true, true, true, false, false><<<gemmBlks, 256, GEMM_SMEM>>>(nullptr, NN);

    // pooling + head
    pool_kernel<<<GG, DD>>>(gid);
    fc_kernel<<<GG, DD>>>(fc_W, fc_b, fc_bn_g, fc_bn_b);
    cls_kernel<<<GG, DD>>>(cls_W, cls_b, bn_hid_g, bn_hid_b, out);
}

// round 9
// speedup vs baseline: 1.4396x; 1.4396x over previous
#include <cuda_runtime.h>
#include <cuda_fp16.h>
#include <cstdint>

#define NN 100000
#define EE 1600000
#define GG 512
#define DD 128
#define CC 10
#define EPS 1e-5f
#define SB 1024
#define NSB ((NN + SB - 1) / SB)

typedef unsigned long long u64;

// ---------------- device scratch ----------------
__device__ float  g_h[NN * DD];
__device__ __half2 g_h16[NN * (DD / 2)];   // h * ns, fp16, for aggregation gathers
__device__ float  g_X[NN * DD];
__device__ float  g_t[NN];                 // sum of ns over in-edges
__device__ float  g_ns[NN];
__device__ float  g_nd[NN];
__device__ int    g_degO[NN];
__device__ int    g_degI[NN];
__device__ int    g_off[NN + 1];
__device__ int    g_cur[NN];
__device__ int    g_esrc[EE];
__device__ int    g_bsum[128];
__device__ int    g_boff[128];
__device__ float  g_sum[DD], g_sq[DD];
__device__ float  g_Wp[DD * DD], g_cvec[DD], g_bias2[DD];
__device__ float  g_hg[GG * DD], g_hg2[GG * DD];
__device__ float  g_psum[DD], g_psq[DD], g_fsum[DD], g_fsq[DD];

// ---------------- f32x2 helpers ----------------
__device__ __forceinline__ u64 pack2(float lo, float hi) {
    u64 r; asm("mov.b64 %0,{%1,%2};" : "=l"(r) : "f"(lo), "f"(hi)); return r;
}
__device__ __forceinline__ void unpack2(u64 v, float& lo, float& hi) {
    asm("mov.b64 {%0,%1},%2;" : "=f"(lo), "=f"(hi) : "l"(v));
}
__device__ __forceinline__ void fma2(u64& d, u64 a, u64 b) {
    asm("fma.rn.f32x2 %0,%1,%2,%0;" : "+l"(d) : "l"(a), "l"(b));
}

// ---------------- init ----------------
__global__ void init_kernel() {
    int i = blockIdx.x * blockDim.x + threadIdx.x;
    if (i < NN) { g_degO[i] = 0; g_degI[i] = 0; g_t[i] = 0.f; }
    if (i < DD) {
        g_sum[i] = 0.f; g_sq[i] = 0.f;
        g_psum[i] = 0.f; g_psq[i] = 0.f;
        g_fsum[i] = 0.f; g_fsq[i] = 0.f;
    }
}

__global__ void degree_kernel(const int* __restrict__ src, const int* __restrict__ dst) {
    int e = blockIdx.x * blockDim.x + threadIdx.x;
    if (e < EE) {
        atomicAdd(&g_degO[src[e]], 1);
        atomicAdd(&g_degI[dst[e]], 1);
    }
}

// ---------------- 3-pass scan over g_degI ----------------
__global__ void scan1_kernel() {
    __shared__ int wsum[8];
    int b = blockIdx.x, tid = threadIdx.x;
    int base = b * SB + tid * 4;
    int s = 0;
    #pragma unroll
    for (int u = 0; u < 4; u++) { int i = base + u; if (i < NN) s += g_degI[i]; }
    int lane = tid & 31, wid = tid >> 5;
    #pragma unroll
    for (int o = 16; o > 0; o >>= 1) s += __shfl_down_sync(0xffffffffu, s, o);
    if (lane == 0) wsum[wid] = s;
    __syncthreads();
    if (tid == 0) {
        int t = 0;
        #pragma unroll
        for (int w = 0; w < 8; w++) t += wsum[w];
        g_bsum[b] = t;
    }
}

__global__ void scan2_kernel() {
    __shared__ int ws[4];
    int tid = threadIdx.x;
    int lane = tid & 31, wid = tid >> 5;
    int v = (tid < NSB) ? g_bsum[tid] : 0;
    int x = v;
    #pragma unroll
    for (int o = 1; o < 32; o <<= 1) {
        int y = __shfl_up_sync(0xffffffffu, x, o);
        if (lane >= o) x += y;
    }
    if (lane == 31) ws[wid] = x;
    __syncthreads();
    if (tid == 0) {
        int c = 0;
        #pragma unroll
        for (int w = 0; w < 4; w++) { int t = ws[w]; ws[w] = c; c += t; }
    }
    __syncthreads();
    int excl = x - v + ws[wid];
    if (tid < NSB) g_boff[tid] = excl;
    if (tid == 0) g_off[NN] = EE;
}

__global__ void scan3_kernel() {
    __shared__ int wsum[8];
    int b = blockIdx.x, tid = threadIdx.x;
    int base = b * SB + tid * 4;
    int v[4];
    #pragma unroll
    for (int u = 0; u < 4; u++) {
        int i = base + u;
        v[u] = (i < NN) ? g_degI[i] : 0;
    }
    int tot = v[0] + v[1] + v[2] + v[3];
    int lane = tid & 31, wid = tid >> 5;
    int x = tot;
    #pragma unroll
    for (int o = 1; o < 32; o <<= 1) {
        int y = __shfl_up_sync(0xffffffffu, x, o);
        if (lane >= o) x += y;
    }
    if (lane == 31) wsum[wid] = x;
    __syncthreads();
    if (wid == 0 && lane < 8) {
        int w = wsum[lane];
        int xx = w;
        #pragma unroll
        for (int o = 1; o < 8; o <<= 1) {
            int y = __shfl_up_sync(0xffu, xx, o);
            if (lane >= o) xx += y;
        }
        wsum[lane] = xx - w;
    }
    __syncthreads();
    int p = x - tot + wsum[wid] + g_boff[b];
    #pragma unroll
    for (int u = 0; u < 4; u++) {
        int i = base + u;
        if (i < NN) {
            g_off[i] = p; g_cur[i] = p; p += v[u];
            g_nd[i] = rsqrtf((float)max(v[u], 1));
            g_ns[i] = rsqrtf((float)max(g_degO[i], 1));
        }
    }
}

// fill CSR + accumulate sum of ns[src] per dst
__global__ void fill_kernel(const int* __restrict__ src, const int* __restrict__ dst) {
    int e = blockIdx.x * blockDim.x + threadIdx.x;
    if (e < EE) {
        int s = src[e], d = dst[e];
        int p = atomicAdd(&g_cur[d], 1);
        g_esrc[p] = s;
        atomicAdd(&g_t[d], g_ns[s]);
    }
}

// ---------------- BN stats over external input (feat layer only) ----------------
__global__ void stats_in_kernel(const float* __restrict__ x) {
    int c = threadIdx.x;
    float s = 0.f, q = 0.f;
    for (int r = blockIdx.x; r < NN; r += gridDim.x) {
        float v = x[r * DD + c];
        s += v; q += v * v;
    }
    atomicAdd(&g_sum[c], s);
    atomicAdd(&g_sq[c], q);
}

// ---------------- finprep ----------------
__global__ void finprep_kernel(const float* __restrict__ g, const float* __restrict__ b,
                               const float* __restrict__ W, const float* __restrict__ addb,
                               int mode) {
    __shared__ float sa[DD], sbv[DD];
    __shared__ float red[8][DD];
    int tid = threadIdx.x;
    if (tid < DD) {
        float m = g_sum[tid] * (1.0f / NN);
        float v = g_sq[tid] * (1.0f / NN) - m * m;
        float a = g[tid] * rsqrtf(v + EPS);
        sa[tid] = a;
        sbv[tid] = b[tid] - m * a;
    }
    __syncthreads();
    for (int i = tid; i < DD * DD; i += 1024)
        g_Wp[i] = sa[i >> 7] * W[i];
    int n = tid & 127, part = tid >> 7;
    float s = 0.f;
    for (int k = part * 16; k < part * 16 + 16; k++)
        s += sbv[k] * W[k * DD + n];
    red[part][n] = s;
    __syncthreads();
    if (tid < DD) {
        float t = 0.f;
        #pragma unroll
        for (int p = 0; p < 8; p++) t += red[p][n];
        if (mode == 0) g_bias2[n] = addb[n] + t;
        else         { g_cvec[n] = t; g_bias2[n] = addb[n]; }
        g_sum[n] = 0.f; g_sq[n] = 0.f;
    }
}

// ---------------- edge aggregation (fp16 gathers, pre-scaled by ns) ----------------
__global__ void agg_kernel() {
    int warp = (blockIdx.x * blockDim.x + threadIdx.x) >> 5;
    int lane = threadIdx.x & 31;
    if (warp >= NN) return;
    int beg = g_off[warp], end = g_off[warp + 1];
    float a0 = 0.f, a1 = 0.f, a2 = 0.f, a3 = 0.f;
    const uint2* __restrict__ h2 = (const uint2*)g_h16;
    for (int e = beg; e < end; e++) {
        int s = g_esrc[e];
        uint2 hv = h2[(size_t)s * 32 + lane];
        float2 f0 = __half22float2(*(__half2*)&hv.x);
        float2 f1 = __half22float2(*(__half2*)&hv.y);
        a0 += f0.x; a1 += f0.y; a2 += f1.x; a3 += f1.y;
    }
    float nd = g_nd[warp];
    ((float4*)g_X)[warp * 32 + lane] = make_float4(a0 * nd, a1 * nd, a2 * nd, a3 * nd);
}

// ---------------- main GEMM (f32x2, R4-proven mainloop) ----------------
template <bool RESID, bool HAST, bool XG, bool STATS, bool WH16>
__global__ void __launch_bounds__(256, 2)
gemm_kernel(const float* __restrict__ Xext, int nrows) {
    __shared__ float Xs[32][129];   // transposed, pad 1 -> conflict-free
    __shared__ float Ws[32][128];
    const float* __restrict__ X = XG ? g_X : Xext;
    int tid = threadIdx.x;
    int m0g = blockIdx.x * 128;
    int tx = tid & 15, ty = tid >> 4;
    int mm = ty * 8, nn = tx * 8;
    u64 acc[8][4];
    #pragma unroll
    for (int i = 0; i < 8; i++)
        #pragma unroll
        for (int j = 0; j < 4; j++) acc[i][j] = pack2(0.f, 0.f);

    for (int kc = 0; kc < 4; kc++) {
        int k0 = kc * 32;
        #pragma unroll
        for (int it = 0; it < 4; it++) {
            int idx = tid + it * 256;
            int row = idx >> 3, kq = idx & 7;
            int gr = m0g + row;
            float4 v = make_float4(0.f, 0.f, 0.f, 0.f);
            if (gr < nrows) v = *(const float4*)(X + gr * DD + k0 + kq * 4);
            Xs[kq * 4 + 0][row] = v.x;
            Xs[kq * 4 + 1][row] = v.y;
            Xs[kq * 4 + 2][row] = v.z;
            Xs[kq * 4 + 3][row] = v.w;
        }
        #pragma unroll
        for (int it = 0; it < 4; it++) {
            int idx = tid + it * 256;
            int kr = idx >> 5, nq = idx & 31;
            *(float4*)&Ws[kr][nq * 4] = *(const float4*)(g_Wp + (k0 + kr) * DD + nq * 4);
        }
        __syncthreads();
        #pragma unroll
        for (int k = 0; k < 32; k++) {
            float xr[8];
            #pragma unroll
            for (int i = 0; i < 8; i++) xr[i] = Xs[k][mm + i];
            ulonglong2 wa = *(const ulonglong2*)&Ws[k][nn];
            ulonglong2 wb = *(const ulonglong2*)&Ws[k][nn + 4];
            u64 w0 = wa.x, w1 = wa.y, w2 = wb.x, w3 = wb.y;
            #pragma unroll
            for (int i = 0; i < 8; i++) {
                u64 xp = pack2(xr[i], xr[i]);
                fma2(acc[i][0], xp, w0);
                fma2(acc[i][1], xp, w1);
                fma2(acc[i][2], xp, w2);
                fma2(acc[i][3], xp, w3);
            }
        }
        __syncthreads();
    }

    // epilogue
    float colsum[8], colsq[8];
    #pragma unroll
    for (int j = 0; j < 8; j++) { colsum[j] = 0.f; colsq[j] = 0.f; }

    #pragma unroll
    for (int i = 0; i < 8; i++) {
        int row = m0g + mm + i;
        bool ok = row < nrows;
        float tval = (HAST && ok) ? g_t[row] * g_nd[row] : 0.f;
        float nsv = (WH16 && ok) ? g_ns[row] : 0.f;
        #pragma unroll
        for (int jp = 0; jp < 4; jp++) {
            float v0, v1;
            unpack2(acc[i][jp], v0, v1);
            int n0 = nn + jp * 2;
            float va = v0 + g_bias2[n0];
            float vb = v1 + g_bias2[n0 + 1];
            if (HAST) { va += tval * g_cvec[n0]; vb += tval * g_cvec[n0 + 1]; }
            va = fmaxf(va, 0.f); vb = fmaxf(vb, 0.f);
            if (ok) {
                float oa, ob;
                if (RESID) {
                    oa = g_h[row * DD + n0] + va;
                    ob = g_h[row * DD + n0 + 1] + vb;
                } else { oa = va; ob = vb; }
                g_h[row * DD + n0] = oa;
                g_h[row * DD + n0 + 1] = ob;
                if (WH16)
                    g_h16[(row * DD + n0) >> 1] = __floats2half2_rn(oa * nsv, ob * nsv);
                if (STATS) {
                    colsum[jp * 2] += oa;     colsq[jp * 2] += oa * oa;
                    colsum[jp * 2 + 1] += ob; colsq[jp * 2 + 1] += ob * ob;
                }
            }
        }
    }

    if (STATS) {
        float* sred = (float*)Xs;
        float* sqd  = (float*)Ws;
        #pragma unroll
        for (int j = 0; j < 8; j++) {
            sred[ty * 128 + nn + j] = colsum[j];
            sqd[ty * 128 + nn + j]  = colsq[j];
        }
        __syncthreads();
        if (tid < 128) {
            float s = 0.f, q = 0.f;
            #pragma unroll
            for (int t2 = 0; t2 < 16; t2++) {
                s += sred[t2 * 128 + tid];
                q += sqd[t2 * 128 + tid];
            }
            atomicAdd(&g_sum[tid], s);
            atomicAdd(&g_sq[tid], q);
        }
    }
}

// ---------------- pooling + head ----------------
__global__ void pool_kernel(const int* __restrict__ gid) {
    int g = blockIdx.x, c = threadIdx.x;
    int lo = 0, hi = NN;
    while (lo < hi) { int mid = (lo + hi) >> 1; if (gid[mid] < g) lo = mid + 1; else hi = mid; }
    int s0 = lo;
    lo = s0; hi = NN;
    while (lo < hi) { int mid = (lo + hi) >> 1; if (gid[mid] < g + 1) lo = mid + 1; else hi = mid; }
    int s1 = lo;
    float s = 0.f;
    for (int r = s0; r < s1; r++) s += g_h[r * DD + c];
    g_hg[g * DD + c] = s;
    atomicAdd(&g_psum[c], s);
    atomicAdd(&g_psq[c], s * s);
}

__global__ void fc_kernel(const float* __restrict__ W, const float* __restrict__ bias,
                          const float* __restrict__ gma, const float* __restrict__ bta) {
    __shared__ float x[DD];
    int r = blockIdx.x, c = threadIdx.x;
    float m = g_psum[c] * (1.0f / GG);
    float v = g_psq[c] * (1.0f / GG) - m * m;
    float a = gma[c] * rsqrtf(v + EPS);
    float bv = bta[c] - m * a;
    x[c] = g_hg[r * DD + c] * a + bv;
    __syncthreads();
    float s = bias[c];
    #pragma unroll 8
    for (int k = 0; k < DD; k++) s += x[k] * W[k * DD + c];
    float o = fmaxf(s, 0.f);
    g_hg2[r * DD + c] = o;
    atomicAdd(&g_fsum[c], o);
    atomicAdd(&g_fsq[c], o * o);
}

__global__ void cls_kernel(const float* __restrict__ W, const float* __restrict__ bias,
                           const float* __restrict__ gma, const float* __restrict__ bta,
                           float* __restrict__ out) {
    __shared__ float x[DD];
    int r = blockIdx.x, c = threadIdx.x;
    float m = g_fsum[c] * (1.0f / GG);
    float v = g_fsq[c] * (1.0f / GG) - m * m;
    float a = gma[c] * rsqrtf(v + EPS);
    float bv = bta[c] - m * a;
    x[c] = g_hg2[r * DD + c] * a + bv;
    __syncthreads();
    if (c < CC) {
        float s = bias[c];
        for (int k = 0; k < DD; k++) s += x[k] * W[k * CC + c];
        out[r * CC + c] = s;
    }
}

// ---------------- launch (forked graph: preprocess ∥ feat layer) ----------------
extern "C" void kernel_launch(void* const* d_in, const int* in_sizes, int n_in,
                              void* d_out, int out_size) {
    const float* h_in      = (const float*)d_in[0];
    const float* bn_feat_g = (const float*)d_in[1];
    const float* bn_feat_b = (const float*)d_in[2];
    const float* feat_W    = (const float*)d_in[3];
    const float* feat_b    = (const float*)d_in[4];
    const float* conv_bn_g = (const float*)d_in[5];
    const float* conv_bn_b = (const float*)d_in[6];
    const float* conv_W    = (const float*)d_in[7];
    const float* conv_b    = (const float*)d_in[8];
    const float* fc_bn_g   = (const float*)d_in[9];
    const float* fc_bn_b   = (const float*)d_in[10];
    const float* fc_W      = (const float*)d_in[11];
    const float* fc_b      = (const float*)d_in[12];
    const float* bn_hid_g  = (const float*)d_in[13];
    const float* bn_hid_b  = (const float*)d_in[14];
    const float* cls_W     = (const float*)d_in[15];
    const float* cls_b     = (const float*)d_in[16];
    const int*   src       = (const int*)d_in[17];
    const int*   dst       = (const int*)d_in[18];
    const int*   gid       = (const int*)d_in[19];
    float* out = (float*)d_out;

    const int nblkN = (NN + 255) / 256;
    const int nblkE = (EE + 255) / 256;
    const int gemmBlks = (NN + 127) / 128;
    const int aggBlks = (NN * 32 + 255) / 256;

    static cudaStream_t s2 = nullptr;
    static cudaEvent_t e0, eFill, eG[3], eP[3];
    if (s2 == nullptr) {
        cudaStreamCreateWithFlags(&s2, cudaStreamNonBlocking);
        cudaEventCreateWithFlags(&e0, cudaEventDisableTiming);
        cudaEventCreateWithFlags(&eFill, cudaEventDisableTiming);
        for (int i = 0; i < 3; i++) {
            cudaEventCreateWithFlags(&eG[i], cudaEventDisableTiming);
            cudaEventCreateWithFlags(&eP[i], cudaEventDisableTiming);
        }
    }
    cudaStream_t ms = 0;   // capture (main) stream

    // root
    init_kernel<<<nblkN, 256, 0, ms>>>();
    cudaEventRecord(e0, ms);

    // branch B (side stream): graph structure
    cudaStreamWaitEvent(s2, e0, 0);
    degree_kernel<<<nblkE, 256, 0, s2>>>(src, dst);
    scan1_kernel<<<NSB, 256, 0, s2>>>();
    scan2_kernel<<<1, 128, 0, s2>>>();
    scan3_kernel<<<NSB, 256, 0, s2>>>();
    fill_kernel<<<nblkE, 256, 0, s2>>>(src, dst);
    cudaEventRecord(eFill, s2);

    // branch A (main stream): feat layer
    stats_in_kernel<<<512, DD, 0, ms>>>(h_in);
    finprep_kernel<<<1, 1024, 0, ms>>>(bn_feat_g, bn_feat_b, feat_W, feat_b, 0);
    gemm_kernel<false, false, false, true, true><<<gemmBlks, 256, 0, ms>>>(h_in, NN);

    // conv layers: finprep_i on side stream overlaps agg_i on main
    const float* cW[3] = {conv_W, conv_W + DD * DD, conv_W + 2 * DD * DD};
    cudaEventRecord(eG[0], ms);
    cudaStreamWaitEvent(ms, eFill, 0);   // agg needs CSR
    for (int i = 0; i < 3; i++) {
        cudaStreamWaitEvent(s2, eG[i], 0);
        finprep_kernel<<<1, 1024, 0, s2>>>(conv_bn_g + i * DD, conv_bn_b + i * DD,
                                           cW[i], conv_b + i * DD, 1);
        cudaEventRecord(eP[i], s2);

        agg_kernel<<<aggBlks, 256, 0, ms>>>();
        cudaStreamWaitEvent(ms, eP[i], 0);
        if (i < 2) {
            gemm_kernel<true, true, true, true, true><<<gemmBlks, 256, 0, ms>>>(nullptr, NN);
            cudaEventRecord(eG[i + 1], ms);
        } else {
            gemm_kernel<true, true, true, false, false><<<gemmBlks, 256, 0, ms>>>(nullptr, NN);
        }
    }

    // pooling + head
    pool_kernel<<<GG, DD, 0, ms>>>(gid);
    fc_kernel<<<GG, DD, 0, ms>>>(fc_W, fc_b, fc_bn_g, fc_bn_b);
    cls_kernel<<<GG, DD, 0, ms>>>(cls_W, cls_b, bn_hid_g, bn_hid_b, out);
}